// round 13
// baseline (speedup 1.0000x reference)
#include <cuda_runtime.h>
#include <cuda_fp16.h>
#include <cstdint>

#define BATCH 128
#define T1    196
#define T2    392
#define ENC   1024
#define DEC   512
#define VV    98
#define MM    294

// fp16 GEMM tiles (frozen mainloop config) + split-K x2
#define BM 128
#define BN 128
#define BKH 64                  // K halves per slab (128 B rows)
#define NSLAB_H 8               // slabs per K-half (ENC/BKH/2)
#define A_STAGE (BM * 128)      // 16 KB
#define B_STAGE (BN * 128)      // 16 KB
#define SMEM_DYN (2 * (A_STAGE + B_STAGE))  // 64 KB
#define N_TILES ((BATCH * VV / BM) * (DEC / BN))   // 392
#define N_CTAS  (2 * N_TILES)                       // 784

// prep-kernel roles: map | fill-all | convert-x | convert-W
#define MAPB   BATCH            // 128
#define FILB   (2 * BATCH)      // 256 (2 blocks per batch)
#define CVXB   512
#define CVWB   16
#define PREPB  (MAPB + FILB + CVXB + CVWB)  // 912

__device__ int g_vis[BATCH * VV];
__device__ __align__(16) __half g_xh[(size_t)BATCH * VV * ENC];  // 25.7 MB
__device__ __align__(16) __half g_wh[DEC * ENC];                 // 1 MB

// ---------------------------------------------------------------------------
__device__ __forceinline__ uint32_t smem_u32(const void* p) {
    uint32_t a;
    asm("{ .reg .u64 t; cvta.to.shared.u64 t, %1; cvt.u32.u64 %0, t; }"
        : "=r"(a) : "l"(p));
    return a;
}
__device__ __forceinline__ void cp16(uint32_t dst, const void* src) {
    asm volatile("cp.async.cg.shared.global [%0], [%1], 16;"
                 :: "r"(dst), "l"(src));
}
#define CP_COMMIT() asm volatile("cp.async.commit_group;" ::: "memory")
#define CP_WAIT(n)  asm volatile("cp.async.wait_group %0;" :: "n"(n) : "memory")

__device__ __forceinline__ void ldsm4(uint32_t* r, uint32_t addr) {
    asm volatile("ldmatrix.sync.aligned.m8n8.x4.shared.b16 {%0,%1,%2,%3}, [%4];"
                 : "=r"(r[0]), "=r"(r[1]), "=r"(r[2]), "=r"(r[3]) : "r"(addr));
}
__device__ __forceinline__ void mma_f16(float* c, const uint32_t* a,
                                        uint32_t b0, uint32_t b1) {
    asm volatile(
        "mma.sync.aligned.m16n8k16.row.col.f32.f16.f16.f32 "
        "{%0,%1,%2,%3}, {%4,%5,%6,%7}, {%8,%9}, {%0,%1,%2,%3};"
        : "+f"(c[0]), "+f"(c[1]), "+f"(c[2]), "+f"(c[3])
        : "r"(a[0]), "r"(a[1]), "r"(a[2]), "r"(a[3]), "r"(b0), "r"(b1));
}
__device__ __forceinline__ uint32_t h2u(float a, float b) {
    __half2 h = __floats2half2_rn(a, b);
    return *reinterpret_cast<uint32_t*>(&h);
}
__device__ __forceinline__ void red2(float* p, float a, float b) {
    asm volatile("red.global.add.f32 [%0], %1;" :: "l"(p), "f"(a) : "memory");
    asm volatile("red.global.add.f32 [%0], %1;" :: "l"(p + 1), "f"(b) : "memory");
}

// shared helper: detect int64 vs int32 layout of masked_ids (per block)
__device__ __forceinline__ int detect_is64(const void* masked_ids, int tid,
                                           int* s_any) {
    if (tid == 0) *s_any = 0;
    __syncthreads();
    const int* w = (const int*)masked_ids;
    int acc = 0;
    for (int i = 1 + 2 * tid; i < 1000; i += 2 * 512) acc |= w[i];
    if (acc) atomicOr(s_any, 1);
    __syncthreads();
    return (*s_any == 0);
}

// build flag[T2] (1=visible) for batch b into smem
__device__ __forceinline__ void build_flags(const void* masked_ids, int b,
                                            int is64, int tid, int* flag) {
    if (tid < T2) flag[tid] = 1;
    __syncthreads();
    for (int i = tid; i < MM; i += 512) {
        int id;
        if (is64) id = (int)((const long long*)masked_ids)[(size_t)b * MM + i];
        else      id = ((const int*)masked_ids)[(size_t)b * MM + i];
        flag[id] = 0;
    }
    __syncthreads();
}

// ---------------------------------------------------------------------------
// Prep kernel, 512 threads/block, 4 independent roles:
//  [0,128):    per-batch map -> g_vis
//  [128,384):  per-half-batch FULL fill of out:
//                masked rows : mask_token + pos + ve
//                visible rows: bias + pos + ve   (base for split-K RED adds)
//  [384,896):  convert x -> g_xh (streaming)
//  [896,912):  convert W -> g_wh
// ---------------------------------------------------------------------------
__global__ __launch_bounds__(512)
void prep_kernel(const float* __restrict__ x,
                 const void* __restrict__ masked_ids,
                 const float* __restrict__ W,
                 const float* __restrict__ bias,
                 const float* __restrict__ mask_token,
                 const float* __restrict__ pos_embed,
                 const float* __restrict__ view_embed,
                 float4* __restrict__ out) {
    const int bid = blockIdx.x;
    const int tid = threadIdx.x;

    if (bid < MAPB) {
        // ---- visibility map for batch b
        __shared__ int flag[T2];
        __shared__ int s[512];
        __shared__ int s_any;
        const int b = bid;
        const int is64 = detect_is64(masked_ids, tid, &s_any);
        build_flags(masked_ids, b, is64, tid, flag);

        const int f = (tid < T2) ? flag[tid] : 0;
        s[tid] = f;
        __syncthreads();
        #pragma unroll
        for (int off = 1; off < 512; off <<= 1) {
            int v = (tid >= off) ? s[tid - off] : 0;
            __syncthreads();
            s[tid] += v;
            __syncthreads();
        }
        if (f) g_vis[b * VV + (s[tid] - f)] = tid;
    } else if (bid < MAPB + FILB) {
        // ---- full fill: base value for every row
        __shared__ int flag[T2];
        __shared__ int s_any;
        const int fb = bid - MAPB;
        const int b = fb >> 1;
        const int half = fb & 1;
        const int is64 = detect_is64(masked_ids, tid, &s_any);
        build_flags(masked_ids, b, is64, tid, flag);

        const int D4 = DEC / 4;          // 128
        const int sub = tid >> 7;        // 0..3
        const int d4 = tid & 127;
        const float4 mt = ((const float4*)mask_token)[d4];
        const float4 bi = ((const float4*)bias)[d4];
        const float4* pos4 = (const float4*)pos_embed;
        const float4* ve4  = (const float4*)view_embed;
        float4* obase = out + (size_t)b * T2 * D4;

        const int t0 = half * T1;        // [0,196) or [196,392)
        for (int t = t0 + sub; t < t0 + T1; t += 4) {
            const float4 base = flag[t] ? bi : mt;   // visible : masked
            float4 p = pos4[t * D4 + d4];
            float4 v = ve4[(t >= T1 ? D4 : 0) + d4];
            float4 r = make_float4(base.x + p.x + v.x, base.y + p.y + v.y,
                                   base.z + p.z + v.z, base.w + p.w + v.w);
            __stcs(&obase[t * D4 + d4], r);
        }
    } else if (bid < MAPB + FILB + CVXB) {
        // ---- convert x -> g_xh: 8 floats/thread, streaming
        const long long N8 = (long long)BATCH * VV * ENC / 8;
        const float4* src = (const float4*)x;
        uint4* dst = (uint4*)g_xh;
        for (long long i = (long long)(bid - MAPB - FILB) * 512 + tid; i < N8;
             i += (long long)CVXB * 512) {
            float4 v0 = __ldcs(src + 2 * i);
            float4 v1 = __ldcs(src + 2 * i + 1);
            uint4 o;
            o.x = h2u(v0.x, v0.y);
            o.y = h2u(v0.z, v0.w);
            o.z = h2u(v1.x, v1.y);
            o.w = h2u(v1.z, v1.w);
            __stcs(dst + i, o);
        }
    } else {
        // ---- convert W -> g_wh
        const int N8 = DEC * ENC / 8;
        const float4* src = (const float4*)W;
        uint4* dst = (uint4*)g_wh;
        for (int i = (bid - MAPB - FILB - CVXB) * 512 + tid; i < N8;
             i += CVWB * 512) {
            float4 v0 = __ldcs(src + 2 * i);
            float4 v1 = __ldcs(src + 2 * i + 1);
            uint4 o;
            o.x = h2u(v0.x, v0.y);
            o.y = h2u(v0.z, v0.w);
            o.z = h2u(v1.x, v1.y);
            o.w = h2u(v1.z, v1.w);
            __stcs(dst + i, o);
        }
    }
}

// ---------------------------------------------------------------------------
// fp16 mma.sync GEMM, split-K x2: 784 CTAs, each computes a 128x128 tile
// over half of K (8 slabs) and RED.ADDs its partial onto the pre-filled base.
// Mainloop body identical to the frozen 57-µs kernel.
// ---------------------------------------------------------------------------
__global__ __launch_bounds__(256, 2)
void gemm_tc_kernel(float* __restrict__ out) {
    extern __shared__ char smem_raw[];
    const uint32_t A0 = smem_u32(smem_raw);
    const uint32_t B0 = A0 + 2 * A_STAGE;

    const int tid = threadIdx.x;
    const int wid = tid >> 5, lid = tid & 31;
    const int wm = wid >> 1, wn = wid & 1;
    const int khalf = blockIdx.x & 1;
    const int tile  = blockIdx.x >> 1;
    const int m0 = (tile >> 2) * BM;
    const int n0 = (tile & 3) * BN;
    const int kbase = khalf * NSLAB_H;   // slab offset

    // loader mapping: 2 threads/row, 4 x 16B chunks each (128 B/row)
    const int rA = tid >> 1;
    const int q0 = (tid & 1) * 4;
    const uint32_t rsw = (rA & 7) << 4;
    const __half* xsrc = g_xh + (size_t)(m0 + rA) * ENC + kbase * BKH + q0 * 8;
    const __half* wsrc = g_wh + (size_t)(n0 + rA) * ENC + kbase * BKH + q0 * 8;
    const uint32_t adst = rA * 128 + ((q0 * 16) ^ rsw);

    // fragment addresses
    const int a_row0 = wm * 32 + ((lid >> 3 & 1) << 3) + (lid & 7);
    const uint32_t a_kb = ((lid >> 4) & 1) * 16;
    const uint32_t a_swz0 = (a_row0 & 7) << 4;
    const uint32_t a_base0 = a_row0 * 128;
    const int b_row0 = wn * 64 + (((lid >> 4) & 1) << 3) + (lid & 7);
    const uint32_t b_kb = ((lid >> 3) & 1) * 16;
    const uint32_t b_swz0 = (b_row0 & 7) << 4;
    const uint32_t b_base0 = b_row0 * 128;

    float acc[2][8][4];
    #pragma unroll
    for (int f = 0; f < 2; f++)
        #pragma unroll
        for (int nf = 0; nf < 8; nf++)
            #pragma unroll
            for (int i = 0; i < 4; i++) acc[f][nf][i] = 0.f;

    // prologue: slabs 0,1 of this K-half
    #pragma unroll
    for (int st = 0; st < 2; st++) {
        #pragma unroll
        for (int i = 0; i < 4; i++) {
            cp16(A0 + st * A_STAGE + (adst ^ (i * 16)), xsrc + st * BKH + i * 8);
            cp16(B0 + st * B_STAGE + (adst ^ (i * 16)), wsrc + st * BKH + i * 8);
        }
        CP_COMMIT();
    }

    for (int k = 0; k < NSLAB_H; k++) {
        const int s = k & 1;
        CP_WAIT(1);
        __syncthreads();

        const uint32_t As = A0 + s * A_STAGE;
        const uint32_t Bs = B0 + s * B_STAGE;
        #pragma unroll
        for (int ks = 0; ks < 4; ks++) {       // 4 x k16 per 64-half slab
            const uint32_t k0b = ks * 32;      // 16 halves = 32 B
            uint32_t a[2][4], bb[4][4];
            #pragma unroll
            for (int f = 0; f < 2; f++)
                ldsm4(a[f], As + a_base0 + f * (16 * 128) +
                             ((a_kb + k0b) ^ a_swz0));
            #pragma unroll
            for (int p = 0; p < 4; p++)
                ldsm4(bb[p], Bs + b_base0 + p * (16 * 128) +
                             ((b_kb + k0b) ^ b_swz0));
            #pragma unroll
            for (int f = 0; f < 2; f++)
                #pragma unroll
                for (int p = 0; p < 4; p++) {
                    mma_f16(acc[f][2 * p],     a[f], bb[p][0], bb[p][1]);
                    mma_f16(acc[f][2 * p + 1], a[f], bb[p][2], bb[p][3]);
                }
        }
        __syncthreads();

        if (k + 2 < NSLAB_H) {
            #pragma unroll
            for (int i = 0; i < 4; i++) {
                cp16(A0 + s * A_STAGE + (adst ^ (i * 16)),
                     xsrc + (k + 2) * BKH + i * 8);
                cp16(B0 + s * B_STAGE + (adst ^ (i * 16)),
                     wsrc + (k + 2) * BKH + i * 8);
            }
        }
        CP_COMMIT();
    }

    // scatter epilogue: RED.ADD partial acc onto pre-filled base
    const int g  = lid >> 2;
    const int nc = 2 * (lid & 3);
    const int nbase = n0 + wn * 64;
    #pragma unroll
    for (int f = 0; f < 2; f++) {
        #pragma unroll
        for (int h = 0; h < 2; h++) {
            const int m = m0 + wm * 32 + f * 16 + h * 8 + g;
            const int b = m / VV;
            const int t = g_vis[m];
            float* orow = out + ((size_t)b * T2 + t) * DEC + nbase;
            #pragma unroll
            for (int nf = 0; nf < 8; nf++) {
                const int n = nf * 8 + nc;
                red2(orow + n, acc[f][nf][2 * h + 0], acc[f][nf][2 * h + 1]);
            }
        }
    }
}

// ---------------------------------------------------------------------------
extern "C" void kernel_launch(void* const* d_in, const int* in_sizes, int n_in,
                              void* d_out, int out_size) {
    const float* x          = (const float*)d_in[0];
    const void*  masked_ids = d_in[1];
    const float* W          = (const float*)d_in[2];
    const float* bias       = (const float*)d_in[3];
    const float* mask_token = (const float*)d_in[4];
    const float* pos_embed  = (const float*)d_in[5];
    const float* view_embed = (const float*)d_in[6];
    float* out = (float*)d_out;

    prep_kernel<<<PREPB, 512>>>(x, masked_ids, W, bias, mask_token, pos_embed,
                                view_embed, (float4*)out);

    static int smem_set = 0;
    if (!smem_set) {
        cudaFuncSetAttribute(gemm_tc_kernel,
                             cudaFuncAttributeMaxDynamicSharedMemorySize, SMEM_DYN);
        smem_set = 1;
    }
    gemm_tc_kernel<<<N_CTAS, 256, SMEM_DYN>>>(out);
}

// round 14
// speedup vs baseline: 1.0819x; 1.0819x over previous
#include <cuda_runtime.h>
#include <cuda_fp16.h>
#include <cstdint>

#define BATCH 128
#define T1    196
#define T2    392
#define ENC   1024
#define DEC   512
#define VV    98
#define MM    294

// fp16 GEMM tiles; 3-stage cp.async pipeline
#define BM 128
#define BN 128
#define BKH 64                 // K halves per slab (128 B rows)
#define NSLAB (ENC / BKH)      // 16
#define NSTAGE 3
#define A_STAGE (BM * 128)     // 16 KB
#define B_STAGE (BN * 128)     // 16 KB
#define SMEM_DYN (NSTAGE * (A_STAGE + B_STAGE))  // 96 KB

// prep-kernel roles: map | fill | convert-x | convert-W  (R11, frozen)
#define MAPB   BATCH           // 128
#define FILB   (2 * BATCH)     // 256
#define CVXB   512
#define CVWB   16
#define PREPB  (MAPB + FILB + CVXB + CVWB)  // 912

__device__ int g_vis[BATCH * VV];
__device__ __align__(16) __half g_xh[(size_t)BATCH * VV * ENC];  // 25.7 MB
__device__ __align__(16) __half g_wh[DEC * ENC];                 // 1 MB

// ---------------------------------------------------------------------------
__device__ __forceinline__ uint32_t smem_u32(const void* p) {
    uint32_t a;
    asm("{ .reg .u64 t; cvta.to.shared.u64 t, %1; cvt.u32.u64 %0, t; }"
        : "=r"(a) : "l"(p));
    return a;
}
__device__ __forceinline__ void cp16(uint32_t dst, const void* src) {
    asm volatile("cp.async.cg.shared.global [%0], [%1], 16;"
                 :: "r"(dst), "l"(src));
}
#define CP_COMMIT() asm volatile("cp.async.commit_group;" ::: "memory")
#define CP_WAIT(n)  asm volatile("cp.async.wait_group %0;" :: "n"(n) : "memory")

__device__ __forceinline__ void ldsm4(uint32_t* r, uint32_t addr) {
    asm volatile("ldmatrix.sync.aligned.m8n8.x4.shared.b16 {%0,%1,%2,%3}, [%4];"
                 : "=r"(r[0]), "=r"(r[1]), "=r"(r[2]), "=r"(r[3]) : "r"(addr));
}
__device__ __forceinline__ void mma_f16(float* c, const uint32_t* a,
                                        uint32_t b0, uint32_t b1) {
    asm volatile(
        "mma.sync.aligned.m16n8k16.row.col.f32.f16.f16.f32 "
        "{%0,%1,%2,%3}, {%4,%5,%6,%7}, {%8,%9}, {%0,%1,%2,%3};"
        : "+f"(c[0]), "+f"(c[1]), "+f"(c[2]), "+f"(c[3])
        : "r"(a[0]), "r"(a[1]), "r"(a[2]), "r"(a[3]), "r"(b0), "r"(b1));
}
__device__ __forceinline__ uint32_t h2u(float a, float b) {
    __half2 h = __floats2half2_rn(a, b);
    return *reinterpret_cast<uint32_t*>(&h);
}

// shared helper: detect int64 vs int32 layout of masked_ids (per block)
__device__ __forceinline__ int detect_is64(const void* masked_ids, int tid,
                                           int* s_any) {
    if (tid == 0) *s_any = 0;
    __syncthreads();
    const int* w = (const int*)masked_ids;
    int acc = 0;
    for (int i = 1 + 2 * tid; i < 1000; i += 2 * 512) acc |= w[i];
    if (acc) atomicOr(s_any, 1);
    __syncthreads();
    return (*s_any == 0);
}

// build flag[T2] (1=visible) for batch b into smem
__device__ __forceinline__ void build_flags(const void* masked_ids, int b,
                                            int is64, int tid, int* flag) {
    if (tid < T2) flag[tid] = 1;
    __syncthreads();
    for (int i = tid; i < MM; i += 512) {
        int id;
        if (is64) id = (int)((const long long*)masked_ids)[(size_t)b * MM + i];
        else      id = ((const int*)masked_ids)[(size_t)b * MM + i];
        flag[id] = 0;
    }
    __syncthreads();
}

// ---------------------------------------------------------------------------
// Prep kernel (R11, frozen), 512 threads/block, 4 independent roles:
//  [0,128):    per-batch map -> g_vis
//  [128,384):  per-half-batch masked fill of out (local flag rebuild)
//  [384,896):  convert x -> g_xh (streaming)
//  [896,912):  convert W -> g_wh
// ---------------------------------------------------------------------------
__global__ __launch_bounds__(512)
void prep_kernel(const float* __restrict__ x,
                 const void* __restrict__ masked_ids,
                 const float* __restrict__ W,
                 const float* __restrict__ mask_token,
                 const float* __restrict__ pos_embed,
                 const float* __restrict__ view_embed,
                 float4* __restrict__ out) {
    const int bid = blockIdx.x;
    const int tid = threadIdx.x;

    if (bid < MAPB) {
        __shared__ int flag[T2];
        __shared__ int s[512];
        __shared__ int s_any;
        const int b = bid;
        const int is64 = detect_is64(masked_ids, tid, &s_any);
        build_flags(masked_ids, b, is64, tid, flag);

        const int f = (tid < T2) ? flag[tid] : 0;
        s[tid] = f;
        __syncthreads();
        #pragma unroll
        for (int off = 1; off < 512; off <<= 1) {
            int v = (tid >= off) ? s[tid - off] : 0;
            __syncthreads();
            s[tid] += v;
            __syncthreads();
        }
        if (f) g_vis[b * VV + (s[tid] - f)] = tid;
    } else if (bid < MAPB + FILB) {
        __shared__ int flag[T2];
        __shared__ int s_any;
        const int fb = bid - MAPB;
        const int b = fb >> 1;
        const int half = fb & 1;
        const int is64 = detect_is64(masked_ids, tid, &s_any);
        build_flags(masked_ids, b, is64, tid, flag);

        const int D4 = DEC / 4;          // 128
        const int sub = tid >> 7;        // 0..3
        const int d4 = tid & 127;
        const float4 mt = ((const float4*)mask_token)[d4];
        const float4* pos4 = (const float4*)pos_embed;
        const float4* ve4  = (const float4*)view_embed;
        float4* obase = out + (size_t)b * T2 * D4;

        const int t0 = half * T1;
        for (int t = t0 + sub; t < t0 + T1; t += 4) {
            if (flag[t]) continue;       // visible -> gemm writes it later
            float4 p = pos4[t * D4 + d4];
            float4 v = ve4[(t >= T1 ? D4 : 0) + d4];
            float4 r = make_float4(mt.x + p.x + v.x, mt.y + p.y + v.y,
                                   mt.z + p.z + v.z, mt.w + p.w + v.w);
            __stcs(&obase[t * D4 + d4], r);
        }
    } else if (bid < MAPB + FILB + CVXB) {
        const long long N8 = (long long)BATCH * VV * ENC / 8;
        const float4* src = (const float4*)x;
        uint4* dst = (uint4*)g_xh;
        for (long long i = (long long)(bid - MAPB - FILB) * 512 + tid; i < N8;
             i += (long long)CVXB * 512) {
            float4 v0 = __ldcs(src + 2 * i);
            float4 v1 = __ldcs(src + 2 * i + 1);
            uint4 o;
            o.x = h2u(v0.x, v0.y);
            o.y = h2u(v0.z, v0.w);
            o.z = h2u(v1.x, v1.y);
            o.w = h2u(v1.z, v1.w);
            __stcs(dst + i, o);
        }
    } else {
        const int N8 = DEC * ENC / 8;
        const float4* src = (const float4*)W;
        uint4* dst = (uint4*)g_wh;
        for (int i = (bid - MAPB - FILB - CVXB) * 512 + tid; i < N8;
             i += CVWB * 512) {
            float4 v0 = __ldcs(src + 2 * i);
            float4 v1 = __ldcs(src + 2 * i + 1);
            uint4 o;
            o.x = h2u(v0.x, v0.y);
            o.y = h2u(v0.z, v0.w);
            o.z = h2u(v1.x, v1.y);
            o.w = h2u(v1.z, v1.w);
            __stcs(dst + i, o);
        }
    }
}

// ---------------------------------------------------------------------------
// fp16 mma.sync GEMM: BM=128, BN=128, 8 warps 4m x 2n, 3-stage cp.async,
// ONE __syncthreads per slab, fused scatter epilogue. grid = (4, 98).
// ---------------------------------------------------------------------------
__global__ __launch_bounds__(256, 2)
void gemm_tc_kernel(const float* __restrict__ bias,
                    const float* __restrict__ pos_embed,
                    const float* __restrict__ view_embed,
                    float* __restrict__ out) {
    extern __shared__ char smem_raw[];
    const uint32_t A0 = smem_u32(smem_raw);
    const uint32_t B0 = A0 + NSTAGE * A_STAGE;

    const int tid = threadIdx.x;
    const int wid = tid >> 5, lid = tid & 31;
    const int wm = wid >> 1, wn = wid & 1;
    const int m0 = blockIdx.y * BM;
    const int n0 = blockIdx.x * BN;

    // loader mapping: 2 threads/row, 4 x 16B chunks each (128 B/row)
    const int rA = tid >> 1;
    const int q0 = (tid & 1) * 4;
    const uint32_t rsw = (rA & 7) << 4;
    const __half* xsrc = g_xh + (size_t)(m0 + rA) * ENC + q0 * 8;
    const __half* wsrc = g_wh + (size_t)(n0 + rA) * ENC + q0 * 8;
    const uint32_t adst = rA * 128 + ((q0 * 16) ^ rsw);

    // fragment addresses
    const int a_row0 = wm * 32 + ((lid >> 3 & 1) << 3) + (lid & 7);
    const uint32_t a_kb = ((lid >> 4) & 1) * 16;
    const uint32_t a_swz0 = (a_row0 & 7) << 4;
    const uint32_t a_base0 = a_row0 * 128;
    const int b_row0 = wn * 64 + (((lid >> 4) & 1) << 3) + (lid & 7);
    const uint32_t b_kb = ((lid >> 3) & 1) * 16;
    const uint32_t b_swz0 = (b_row0 & 7) << 4;
    const uint32_t b_base0 = b_row0 * 128;

    float acc[2][8][4];
    #pragma unroll
    for (int f = 0; f < 2; f++)
        #pragma unroll
        for (int nf = 0; nf < 8; nf++)
            #pragma unroll
            for (int i = 0; i < 4; i++) acc[f][nf][i] = 0.f;

    // prologue: slabs 0,1 -> buffers 0,1
    #pragma unroll
    for (int st = 0; st < NSTAGE - 1; st++) {
        #pragma unroll
        for (int i = 0; i < 4; i++) {
            cp16(A0 + st * A_STAGE + (adst ^ (i * 16)), xsrc + st * BKH + i * 8);
            cp16(B0 + st * B_STAGE + (adst ^ (i * 16)), wsrc + st * BKH + i * 8);
        }
        CP_COMMIT();
    }

    int buf = 0;
    for (int k = 0; k < NSLAB; k++) {
        CP_WAIT(1);                // slab k's group arrived (this thread)
        __syncthreads();           // cross-warp visibility; all warps done
                                   // computing slab k-1 => buf (k+2)%3 free

        // issue loads for slab k+2 into buffer (k+2)%3 BEFORE computing k
        if (k + 2 < NSLAB) {
            const int nb = (buf + 2 >= NSTAGE) ? buf + 2 - NSTAGE : buf + 2;
            #pragma unroll
            for (int i = 0; i < 4; i++) {
                cp16(A0 + nb * A_STAGE + (adst ^ (i * 16)),
                     xsrc + (k + 2) * BKH + i * 8);
                cp16(B0 + nb * B_STAGE + (adst ^ (i * 16)),
                     wsrc + (k + 2) * BKH + i * 8);
            }
        }
        CP_COMMIT();               // empty commits keep group accounting

        const uint32_t As = A0 + buf * A_STAGE;
        const uint32_t Bs = B0 + buf * B_STAGE;
        #pragma unroll
        for (int ks = 0; ks < 4; ks++) {       // 4 x k16 per 64-half slab
            const uint32_t k0b = ks * 32;      // 16 halves = 32 B
            uint32_t a[2][4], bb[4][4];
            #pragma unroll
            for (int f = 0; f < 2; f++)
                ldsm4(a[f], As + a_base0 + f * (16 * 128) +
                             ((a_kb + k0b) ^ a_swz0));
            #pragma unroll
            for (int p = 0; p < 4; p++)
                ldsm4(bb[p], Bs + b_base0 + p * (16 * 128) +
                             ((b_kb + k0b) ^ b_swz0));
            #pragma unroll
            for (int f = 0; f < 2; f++)
                #pragma unroll
                for (int p = 0; p < 4; p++) {
                    mma_f16(acc[f][2 * p],     a[f], bb[p][0], bb[p][1]);
                    mma_f16(acc[f][2 * p + 1], a[f], bb[p][2], bb[p][3]);
                }
        }
        buf = (buf + 1 == NSTAGE) ? 0 : buf + 1;
    }

    // fused scatter epilogue
    const int g  = lid >> 2;
    const int nc = 2 * (lid & 3);
    const int nbase = n0 + wn * 64;
    #pragma unroll
    for (int f = 0; f < 2; f++) {
        #pragma unroll
        for (int h = 0; h < 2; h++) {
            const int m = m0 + wm * 32 + f * 16 + h * 8 + g;
            const int b = m / VV;
            const int t = g_vis[m];
            const float* ve   = view_embed + (t >= T1 ? DEC : 0) + nbase;
            const float* bi   = bias + nbase;
            const float* prow = pos_embed + (size_t)t * DEC + nbase;
            float* orow = out + ((size_t)b * T2 + t) * DEC + nbase;
            #pragma unroll
            for (int nf = 0; nf < 8; nf++) {
                const int n = nf * 8 + nc;
                float2 biv = *(const float2*)(bi + n);
                float2 pov = *(const float2*)(prow + n);
                float2 vev = *(const float2*)(ve + n);
                float2 r;
                r.x = acc[f][nf][2 * h + 0] + biv.x + pov.x + vev.x;
                r.y = acc[f][nf][2 * h + 1] + biv.y + pov.y + vev.y;
                *(float2*)(orow + n) = r;
            }
        }
    }
}

// ---------------------------------------------------------------------------
extern "C" void kernel_launch(void* const* d_in, const int* in_sizes, int n_in,
                              void* d_out, int out_size) {
    const float* x          = (const float*)d_in[0];
    const void*  masked_ids = d_in[1];
    const float* W          = (const float*)d_in[2];
    const float* bias       = (const float*)d_in[3];
    const float* mask_token = (const float*)d_in[4];
    const float* pos_embed  = (const float*)d_in[5];
    const float* view_embed = (const float*)d_in[6];
    float* out = (float*)d_out;

    prep_kernel<<<PREPB, 512>>>(x, masked_ids, W, mask_token, pos_embed,
                                view_embed, (float4*)out);

    static int smem_set = 0;
    if (!smem_set) {
        cudaFuncSetAttribute(gemm_tc_kernel,
                             cudaFuncAttributeMaxDynamicSharedMemorySize, SMEM_DYN);
        smem_set = 1;
    }
    dim3 grid(DEC / BN, (BATCH * VV) / BM);  // (4, 98)
    gemm_tc_kernel<<<grid, 256, SMEM_DYN>>>(bias, pos_embed, view_embed, out);
}

// round 16
// speedup vs baseline: 1.1159x; 1.0314x over previous
#include <cuda_runtime.h>
#include <cuda_fp16.h>
#include <cstdint>

#define BATCH 128
#define T1    196
#define T2    392
#define ENC   1024
#define DEC   512
#define VV    98
#define MM    294

// fp16 GEMM tiles (frozen config — do not touch)
#define BM 128
#define BN 128
#define BKH 64                 // K halves per slab (128 B rows)
#define NSLAB (ENC / BKH)      // 16
#define A_STAGE (BM * 128)     // 16 KB
#define B_STAGE (BN * 128)     // 16 KB
#define SMEM_DYN (2 * (A_STAGE + B_STAGE))  // 64 KB

// prep-kernel roles: map | fill | convert-x | convert-W (fine-grained)
#define MAPB   BATCH           // 128
#define FILB   (4 * BATCH)     // 512 (4 blocks per batch, 98 rows each)
#define CVXB   768
#define CVWB   32
#define PREPB  (MAPB + FILB + CVXB + CVWB)  // 1440

__device__ int g_vis[BATCH * VV];
__device__ __align__(16) __half g_xh[(size_t)BATCH * VV * ENC];  // 25.7 MB
__device__ __align__(16) __half g_wh[DEC * ENC];                 // 1 MB

// ---------------------------------------------------------------------------
__device__ __forceinline__ uint32_t smem_u32(const void* p) {
    uint32_t a;
    asm("{ .reg .u64 t; cvta.to.shared.u64 t, %1; cvt.u32.u64 %0, t; }"
        : "=r"(a) : "l"(p));
    return a;
}
__device__ __forceinline__ void cp16(uint32_t dst, const void* src) {
    asm volatile("cp.async.cg.shared.global [%0], [%1], 16;"
                 :: "r"(dst), "l"(src));
}
#define CP_COMMIT() asm volatile("cp.async.commit_group;" ::: "memory")
#define CP_WAIT(n)  asm volatile("cp.async.wait_group %0;" :: "n"(n) : "memory")

__device__ __forceinline__ void ldsm4(uint32_t* r, uint32_t addr) {
    asm volatile("ldmatrix.sync.aligned.m8n8.x4.shared.b16 {%0,%1,%2,%3}, [%4];"
                 : "=r"(r[0]), "=r"(r[1]), "=r"(r[2]), "=r"(r[3]) : "r"(addr));
}
__device__ __forceinline__ void mma_f16(float* c, const uint32_t* a,
                                        uint32_t b0, uint32_t b1) {
    asm volatile(
        "mma.sync.aligned.m16n8k16.row.col.f32.f16.f16.f32 "
        "{%0,%1,%2,%3}, {%4,%5,%6,%7}, {%8,%9}, {%0,%1,%2,%3};"
        : "+f"(c[0]), "+f"(c[1]), "+f"(c[2]), "+f"(c[3])
        : "r"(a[0]), "r"(a[1]), "r"(a[2]), "r"(a[3]), "r"(b0), "r"(b1));
}
__device__ __forceinline__ uint32_t h2u(float a, float b) {
    __half2 h = __floats2half2_rn(a, b);
    return *reinterpret_cast<uint32_t*>(&h);
}

// shared helper: detect int64 vs int32 layout of masked_ids (per block)
__device__ __forceinline__ int detect_is64(const void* masked_ids, int tid,
                                           int* s_any) {
    if (tid == 0) *s_any = 0;
    __syncthreads();
    const int* w = (const int*)masked_ids;
    int acc = 0;
    for (int i = 1 + 2 * tid; i < 1000; i += 2 * 512) acc |= w[i];
    if (acc) atomicOr(s_any, 1);
    __syncthreads();
    return (*s_any == 0);
}

// build flag[T2] (1=visible) for batch b into smem
__device__ __forceinline__ void build_flags(const void* masked_ids, int b,
                                            int is64, int tid, int* flag) {
    if (tid < T2) flag[tid] = 1;
    __syncthreads();
    for (int i = tid; i < MM; i += 512) {
        int id;
        if (is64) id = (int)((const long long*)masked_ids)[(size_t)b * MM + i];
        else      id = ((const int*)masked_ids)[(size_t)b * MM + i];
        flag[id] = 0;
    }
    __syncthreads();
}

// ---------------------------------------------------------------------------
// Prep kernel, 512 threads/block, 4 independent roles (fine-grained blocks):
//  [0,128):     per-batch map -> g_vis
//  [128,640):   per-quarter-batch masked fill of out (local flag rebuild)
//  [640,1408):  convert x -> g_xh (streaming)
//  [1408,1440): convert W -> g_wh
// ---------------------------------------------------------------------------
__global__ __launch_bounds__(512)
void prep_kernel(const float* __restrict__ x,
                 const void* __restrict__ masked_ids,
                 const float* __restrict__ W,
                 const float* __restrict__ mask_token,
                 const float* __restrict__ pos_embed,
                 const float* __restrict__ view_embed,
                 float4* __restrict__ out) {
    const int bid = blockIdx.x;
    const int tid = threadIdx.x;

    if (bid < MAPB) {
        // ---- visibility map for batch b
        __shared__ int flag[T2];
        __shared__ int s[512];
        __shared__ int s_any;
        const int b = bid;
        const int is64 = detect_is64(masked_ids, tid, &s_any);
        build_flags(masked_ids, b, is64, tid, flag);

        const int f = (tid < T2) ? flag[tid] : 0;
        s[tid] = f;
        __syncthreads();
        #pragma unroll
        for (int off = 1; off < 512; off <<= 1) {
            int v = (tid >= off) ? s[tid - off] : 0;
            __syncthreads();
            s[tid] += v;
            __syncthreads();
        }
        if (f) g_vis[b * VV + (s[tid] - f)] = tid;
    } else if (bid < MAPB + FILB) {
        // ---- masked fill: block covers a quarter of one batch's rows
        __shared__ int flag[T2];
        __shared__ int s_any;
        const int fb = bid - MAPB;
        const int b = fb >> 2;
        const int quarter = fb & 3;
        const int is64 = detect_is64(masked_ids, tid, &s_any);
        build_flags(masked_ids, b, is64, tid, flag);

        const int D4 = DEC / 4;          // 128
        const int sub = tid >> 7;        // 0..3
        const int d4 = tid & 127;
        const float4 mt = ((const float4*)mask_token)[d4];
        const float4* pos4 = (const float4*)pos_embed;
        const float4* ve4  = (const float4*)view_embed;
        float4* obase = out + (size_t)b * T2 * D4;

        const int t0 = quarter * VV;     // 98-row spans: 0,98,196,294
        for (int t = t0 + sub; t < t0 + VV; t += 4) {
            if (flag[t]) continue;       // visible -> gemm writes it later
            float4 p = pos4[t * D4 + d4];
            float4 v = ve4[(t >= T1 ? D4 : 0) + d4];
            float4 r = make_float4(mt.x + p.x + v.x, mt.y + p.y + v.y,
                                   mt.z + p.z + v.z, mt.w + p.w + v.w);
            __stcs(&obase[t * D4 + d4], r);
        }
    } else if (bid < MAPB + FILB + CVXB) {
        // ---- convert x -> g_xh: 8 floats/thread, streaming
        const long long N8 = (long long)BATCH * VV * ENC / 8;
        const float4* src = (const float4*)x;
        uint4* dst = (uint4*)g_xh;
        for (long long i = (long long)(bid - MAPB - FILB) * 512 + tid; i < N8;
             i += (long long)CVXB * 512) {
            float4 v0 = __ldcs(src + 2 * i);
            float4 v1 = __ldcs(src + 2 * i + 1);
            uint4 o;
            o.x = h2u(v0.x, v0.y);
            o.y = h2u(v0.z, v0.w);
            o.z = h2u(v1.x, v1.y);
            o.w = h2u(v1.z, v1.w);
            __stcs(dst + i, o);
        }
    } else {
        // ---- convert W -> g_wh
        const int N8 = DEC * ENC / 8;
        const float4* src = (const float4*)W;
        uint4* dst = (uint4*)g_wh;
        for (int i = (bid - MAPB - FILB - CVXB) * 512 + tid; i < N8;
             i += CVWB * 512) {
            float4 v0 = __ldcs(src + 2 * i);
            float4 v1 = __ldcs(src + 2 * i + 1);
            uint4 o;
            o.x = h2u(v0.x, v0.y);
            o.y = h2u(v0.z, v0.w);
            o.z = h2u(v1.x, v1.y);
            o.w = h2u(v1.z, v1.w);
            __stcs(dst + i, o);
        }
    }
}

// ---------------------------------------------------------------------------
// fp16 mma.sync GEMM (frozen 57-µs body, R11 verbatim): BM=128, BN=128,
// 8 warps 4m x 2n, 2-stage cp.async, fused scatter epilogue. grid = (4, 98).
// ---------------------------------------------------------------------------
__global__ __launch_bounds__(256, 2)
void gemm_tc_kernel(const float* __restrict__ bias,
                    const float* __restrict__ pos_embed,
                    const float* __restrict__ view_embed,
                    float* __restrict__ out) {
    extern __shared__ char smem_raw[];
    const uint32_t A0 = smem_u32(smem_raw);
    const uint32_t B0 = A0 + 2 * A_STAGE;

    const int tid = threadIdx.x;
    const int wid = tid >> 5, lid = tid & 31;
    const int wm = wid >> 1, wn = wid & 1;
    const int m0 = blockIdx.y * BM;
    const int n0 = blockIdx.x * BN;

    // loader mapping: 2 threads/row, 4 x 16B chunks each (128 B/row)
    const int rA = tid >> 1;
    const int q0 = (tid & 1) * 4;
    const uint32_t rsw = (rA & 7) << 4;
    const __half* xsrc = g_xh + (size_t)(m0 + rA) * ENC + q0 * 8;
    const __half* wsrc = g_wh + (size_t)(n0 + rA) * ENC + q0 * 8;
    const uint32_t adst = rA * 128 + ((q0 * 16) ^ rsw);

    // fragment addresses
    const int a_row0 = wm * 32 + ((lid >> 3 & 1) << 3) + (lid & 7);
    const uint32_t a_kb = ((lid >> 4) & 1) * 16;
    const uint32_t a_swz0 = (a_row0 & 7) << 4;
    const uint32_t a_base0 = a_row0 * 128;
    const int b_row0 = wn * 64 + (((lid >> 4) & 1) << 3) + (lid & 7);
    const uint32_t b_kb = ((lid >> 3) & 1) * 16;
    const uint32_t b_swz0 = (b_row0 & 7) << 4;
    const uint32_t b_base0 = b_row0 * 128;

    float acc[2][8][4];
    #pragma unroll
    for (int f = 0; f < 2; f++)
        #pragma unroll
        for (int nf = 0; nf < 8; nf++)
            #pragma unroll
            for (int i = 0; i < 4; i++) acc[f][nf][i] = 0.f;

    // prologue: slabs 0,1
    #pragma unroll
    for (int st = 0; st < 2; st++) {
        #pragma unroll
        for (int i = 0; i < 4; i++) {
            cp16(A0 + st * A_STAGE + (adst ^ (i * 16)), xsrc + st * BKH + i * 8);
            cp16(B0 + st * B_STAGE + (adst ^ (i * 16)), wsrc + st * BKH + i * 8);
        }
        CP_COMMIT();
    }

    for (int k = 0; k < NSLAB; k++) {
        const int s = k & 1;
        CP_WAIT(1);
        __syncthreads();

        const uint32_t As = A0 + s * A_STAGE;
        const uint32_t Bs = B0 + s * B_STAGE;
        #pragma unroll
        for (int ks = 0; ks < 4; ks++) {       // 4 x k16 per 64-half slab
            const uint32_t k0b = ks * 32;      // 16 halves = 32 B
            uint32_t a[2][4], bb[4][4];
            #pragma unroll
            for (int f = 0; f < 2; f++)
                ldsm4(a[f], As + a_base0 + f * (16 * 128) +
                             ((a_kb + k0b) ^ a_swz0));
            #pragma unroll
            for (int p = 0; p < 4; p++)
                ldsm4(bb[p], Bs + b_base0 + p * (16 * 128) +
                             ((b_kb + k0b) ^ b_swz0));
            #pragma unroll
            for (int f = 0; f < 2; f++)
                #pragma unroll
                for (int p = 0; p < 4; p++) {
                    mma_f16(acc[f][2 * p],     a[f], bb[p][0], bb[p][1]);
                    mma_f16(acc[f][2 * p + 1], a[f], bb[p][2], bb[p][3]);
                }
        }
        __syncthreads();

        if (k + 2 < NSLAB) {
            #pragma unroll
            for (int i = 0; i < 4; i++) {
                cp16(A0 + s * A_STAGE + (adst ^ (i * 16)),
                     xsrc + (k + 2) * BKH + i * 8);
                cp16(B0 + s * B_STAGE + (adst ^ (i * 16)),
                     wsrc + (k + 2) * BKH + i * 8);
            }
        }
        CP_COMMIT();
    }

    // fused scatter epilogue
    const int g  = lid >> 2;
    const int nc = 2 * (lid & 3);
    const int nbase = n0 + wn * 64;
    #pragma unroll
    for (int f = 0; f < 2; f++) {
        #pragma unroll
        for (int h = 0; h < 2; h++) {
            const int m = m0 + wm * 32 + f * 16 + h * 8 + g;
            const int b = m / VV;
            const int t = g_vis[m];
            const float* ve   = view_embed + (t >= T1 ? DEC : 0) + nbase;
            const float* bi   = bias + nbase;
            const float* prow = pos_embed + (size_t)t * DEC + nbase;
            float* orow = out + ((size_t)b * T2 + t) * DEC + nbase;
            #pragma unroll
            for (int nf = 0; nf < 8; nf++) {
                const int n = nf * 8 + nc;
                float2 biv = *(const float2*)(bi + n);
                float2 pov = *(const float2*)(prow + n);
                float2 vev = *(const float2*)(ve + n);
                float2 r;
                r.x = acc[f][nf][2 * h + 0] + biv.x + pov.x + vev.x;
                r.y = acc[f][nf][2 * h + 1] + biv.y + pov.y + vev.y;
                *(float2*)(orow + n) = r;
            }
        }
    }
}

// ---------------------------------------------------------------------------
extern "C" void kernel_launch(void* const* d_in, const int* in_sizes, int n_in,
                              void* d_out, int out_size) {
    const float* x          = (const float*)d_in[0];
    const void*  masked_ids = d_in[1];
    const float* W          = (const float*)d_in[2];
    const float* bias       = (const float*)d_in[3];
    const float* mask_token = (const float*)d_in[4];
    const float* pos_embed  = (const float*)d_in[5];
    const float* view_embed = (const float*)d_in[6];
    float* out = (float*)d_out;

    prep_kernel<<<PREPB, 512>>>(x, masked_ids, W, mask_token, pos_embed,
                                view_embed, (float4*)out);

    static int smem_set = 0;
    if (!smem_set) {
        cudaFuncSetAttribute(gemm_tc_kernel,
                             cudaFuncAttributeMaxDynamicSharedMemorySize, SMEM_DYN);
        smem_set = 1;
    }
    dim3 grid(DEC / BN, (BATCH * VV) / BM);  // (4, 98)
    gemm_tc_kernel<<<grid, 256, SMEM_DYN>>>(bias, pos_embed, view_embed, out);
}

// round 17
// speedup vs baseline: 1.1219x; 1.0053x over previous
#include <cuda_runtime.h>
#include <cuda_fp16.h>
#include <cstdint>

#define BATCH 128
#define T1    196
#define T2    392
#define ENC   1024
#define DEC   512
#define VV    98
#define MM    294

// fp16 GEMM tiles (frozen config — do not touch)
#define BM 128
#define BN 128
#define BKH 64                 // K halves per slab (128 B rows)
#define NSLAB (ENC / BKH)      // 16
#define A_STAGE (BM * 128)     // 16 KB
#define B_STAGE (BN * 128)     // 16 KB
#define SMEM_DYN (2 * (A_STAGE + B_STAGE))  // 64 KB

// prep-kernel roles: map | convert-x | convert-W
#define MAPB   BATCH           // 128
#define CVXB   768
#define CVWB   32
#define PREPB  (MAPB + CVXB + CVWB)  // 928

#define FILLB  (4 * BATCH)     // 512 fill blocks (quarter-batch each)

__device__ int g_vis[BATCH * VV];
__device__ __align__(16) __half g_xh[(size_t)BATCH * VV * ENC];  // 25.7 MB
__device__ __align__(16) __half g_wh[DEC * ENC];                 // 1 MB

// ---------------------------------------------------------------------------
__device__ __forceinline__ uint32_t smem_u32(const void* p) {
    uint32_t a;
    asm("{ .reg .u64 t; cvta.to.shared.u64 t, %1; cvt.u32.u64 %0, t; }"
        : "=r"(a) : "l"(p));
    return a;
}
__device__ __forceinline__ void cp16(uint32_t dst, const void* src) {
    asm volatile("cp.async.cg.shared.global [%0], [%1], 16;"
                 :: "r"(dst), "l"(src));
}
#define CP_COMMIT() asm volatile("cp.async.commit_group;" ::: "memory")
#define CP_WAIT(n)  asm volatile("cp.async.wait_group %0;" :: "n"(n) : "memory")

__device__ __forceinline__ void ldsm4(uint32_t* r, uint32_t addr) {
    asm volatile("ldmatrix.sync.aligned.m8n8.x4.shared.b16 {%0,%1,%2,%3}, [%4];"
                 : "=r"(r[0]), "=r"(r[1]), "=r"(r[2]), "=r"(r[3]) : "r"(addr));
}
__device__ __forceinline__ void mma_f16(float* c, const uint32_t* a,
                                        uint32_t b0, uint32_t b1) {
    asm volatile(
        "mma.sync.aligned.m16n8k16.row.col.f32.f16.f16.f32 "
        "{%0,%1,%2,%3}, {%4,%5,%6,%7}, {%8,%9}, {%0,%1,%2,%3};"
        : "+f"(c[0]), "+f"(c[1]), "+f"(c[2]), "+f"(c[3])
        : "r"(a[0]), "r"(a[1]), "r"(a[2]), "r"(a[3]), "r"(b0), "r"(b1));
}
__device__ __forceinline__ uint32_t h2u(float a, float b) {
    __half2 h = __floats2half2_rn(a, b);
    return *reinterpret_cast<uint32_t*>(&h);
}

// shared helper: detect int64 vs int32 layout of masked_ids (per block)
__device__ __forceinline__ int detect_is64(const void* masked_ids, int tid,
                                           int* s_any) {
    if (tid == 0) *s_any = 0;
    __syncthreads();
    const int* w = (const int*)masked_ids;
    int acc = 0;
    for (int i = 1 + 2 * tid; i < 1000; i += 2 * 512) acc |= w[i];
    if (acc) atomicOr(s_any, 1);
    __syncthreads();
    return (*s_any == 0);
}

// build flag[T2] (1=visible) for batch b into smem (512-thread blocks)
__device__ __forceinline__ void build_flags(const void* masked_ids, int b,
                                            int is64, int tid, int* flag) {
    if (tid < T2) flag[tid] = 1;
    __syncthreads();
    for (int i = tid; i < MM; i += 512) {
        int id;
        if (is64) id = (int)((const long long*)masked_ids)[(size_t)b * MM + i];
        else      id = ((const int*)masked_ids)[(size_t)b * MM + i];
        flag[id] = 0;
    }
    __syncthreads();
}

// ---------------------------------------------------------------------------
// Prep kernel (stream 0): map + fp16 conversions only.
// ---------------------------------------------------------------------------
__global__ __launch_bounds__(512)
void prep_kernel(const float* __restrict__ x,
                 const void* __restrict__ masked_ids,
                 const float* __restrict__ W) {
    const int bid = blockIdx.x;
    const int tid = threadIdx.x;

    if (bid < MAPB) {
        __shared__ int flag[T2];
        __shared__ int s[512];
        __shared__ int s_any;
        const int b = bid;
        const int is64 = detect_is64(masked_ids, tid, &s_any);
        build_flags(masked_ids, b, is64, tid, flag);

        const int f = (tid < T2) ? flag[tid] : 0;
        s[tid] = f;
        __syncthreads();
        #pragma unroll
        for (int off = 1; off < 512; off <<= 1) {
            int v = (tid >= off) ? s[tid - off] : 0;
            __syncthreads();
            s[tid] += v;
            __syncthreads();
        }
        if (f) g_vis[b * VV + (s[tid] - f)] = tid;
    } else if (bid < MAPB + CVXB) {
        const long long N8 = (long long)BATCH * VV * ENC / 8;
        const float4* src = (const float4*)x;
        uint4* dst = (uint4*)g_xh;
        for (long long i = (long long)(bid - MAPB) * 512 + tid; i < N8;
             i += (long long)CVXB * 512) {
            float4 v0 = __ldcs(src + 2 * i);
            float4 v1 = __ldcs(src + 2 * i + 1);
            uint4 o;
            o.x = h2u(v0.x, v0.y);
            o.y = h2u(v0.z, v0.w);
            o.z = h2u(v1.x, v1.y);
            o.w = h2u(v1.z, v1.w);
            __stcs(dst + i, o);
        }
    } else {
        const int N8 = DEC * ENC / 8;
        const float4* src = (const float4*)W;
        uint4* dst = (uint4*)g_wh;
        for (int i = (bid - MAPB - CVXB) * 512 + tid; i < N8; i += CVWB * 512) {
            float4 v0 = __ldcs(src + 2 * i);
            float4 v1 = __ldcs(src + 2 * i + 1);
            uint4 o;
            o.x = h2u(v0.x, v0.y);
            o.y = h2u(v0.z, v0.w);
            o.z = h2u(v1.x, v1.y);
            o.w = h2u(v1.z, v1.w);
            __stcs(dst + i, o);
        }
    }
}

// ---------------------------------------------------------------------------
// Fill kernel (stream 1, concurrent with gemm): 512 blocks, quarter-batch
// each; writes ONLY masked rows (disjoint from gemm's visible-row scatter).
// ---------------------------------------------------------------------------
__global__ __launch_bounds__(512)
void fill_kernel(const void* __restrict__ masked_ids,
                 const float* __restrict__ mask_token,
                 const float* __restrict__ pos_embed,
                 const float* __restrict__ view_embed,
                 float4* __restrict__ out) {
    __shared__ int flag[T2];
    __shared__ int s_any;
    const int tid = threadIdx.x;
    const int b = blockIdx.x >> 2;
    const int quarter = blockIdx.x & 3;
    const int is64 = detect_is64(masked_ids, tid, &s_any);
    build_flags(masked_ids, b, is64, tid, flag);

    const int D4 = DEC / 4;          // 128
    const int sub = tid >> 7;        // 0..3
    const int d4 = tid & 127;
    const float4 mt = ((const float4*)mask_token)[d4];
    const float4* pos4 = (const float4*)pos_embed;
    const float4* ve4  = (const float4*)view_embed;
    float4* obase = out + (size_t)b * T2 * D4;

    const int t0 = quarter * VV;     // 98-row spans: 0,98,196,294
    for (int t = t0 + sub; t < t0 + VV; t += 4) {
        if (flag[t]) continue;       // visible -> gemm writes it
        float4 p = pos4[t * D4 + d4];
        float4 v = ve4[(t >= T1 ? D4 : 0) + d4];
        float4 r = make_float4(mt.x + p.x + v.x, mt.y + p.y + v.y,
                               mt.z + p.z + v.z, mt.w + p.w + v.w);
        __stcs(&obase[t * D4 + d4], r);
    }
}

// ---------------------------------------------------------------------------
// fp16 mma.sync GEMM (frozen 57-µs body, R11 verbatim): BM=128, BN=128,
// 8 warps 4m x 2n, 2-stage cp.async, fused scatter epilogue. grid = (4, 98).
// ---------------------------------------------------------------------------
__global__ __launch_bounds__(256, 2)
void gemm_tc_kernel(const float* __restrict__ bias,
                    const float* __restrict__ pos_embed,
                    const float* __restrict__ view_embed,
                    float* __restrict__ out) {
    extern __shared__ char smem_raw[];
    const uint32_t A0 = smem_u32(smem_raw);
    const uint32_t B0 = A0 + 2 * A_STAGE;

    const int tid = threadIdx.x;
    const int wid = tid >> 5, lid = tid & 31;
    const int wm = wid >> 1, wn = wid & 1;
    const int m0 = blockIdx.y * BM;
    const int n0 = blockIdx.x * BN;

    // loader mapping: 2 threads/row, 4 x 16B chunks each (128 B/row)
    const int rA = tid >> 1;
    const int q0 = (tid & 1) * 4;
    const uint32_t rsw = (rA & 7) << 4;
    const __half* xsrc = g_xh + (size_t)(m0 + rA) * ENC + q0 * 8;
    const __half* wsrc = g_wh + (size_t)(n0 + rA) * ENC + q0 * 8;
    const uint32_t adst = rA * 128 + ((q0 * 16) ^ rsw);

    // fragment addresses
    const int a_row0 = wm * 32 + ((lid >> 3 & 1) << 3) + (lid & 7);
    const uint32_t a_kb = ((lid >> 4) & 1) * 16;
    const uint32_t a_swz0 = (a_row0 & 7) << 4;
    const uint32_t a_base0 = a_row0 * 128;
    const int b_row0 = wn * 64 + (((lid >> 4) & 1) << 3) + (lid & 7);
    const uint32_t b_kb = ((lid >> 3) & 1) * 16;
    const uint32_t b_swz0 = (b_row0 & 7) << 4;
    const uint32_t b_base0 = b_row0 * 128;

    float acc[2][8][4];
    #pragma unroll
    for (int f = 0; f < 2; f++)
        #pragma unroll
        for (int nf = 0; nf < 8; nf++)
            #pragma unroll
            for (int i = 0; i < 4; i++) acc[f][nf][i] = 0.f;

    // prologue: slabs 0,1
    #pragma unroll
    for (int st = 0; st < 2; st++) {
        #pragma unroll
        for (int i = 0; i < 4; i++) {
            cp16(A0 + st * A_STAGE + (adst ^ (i * 16)), xsrc + st * BKH + i * 8);
            cp16(B0 + st * B_STAGE + (adst ^ (i * 16)), wsrc + st * BKH + i * 8);
        }
        CP_COMMIT();
    }

    for (int k = 0; k < NSLAB; k++) {
        const int s = k & 1;
        CP_WAIT(1);
        __syncthreads();

        const uint32_t As = A0 + s * A_STAGE;
        const uint32_t Bs = B0 + s * B_STAGE;
        #pragma unroll
        for (int ks = 0; ks < 4; ks++) {       // 4 x k16 per 64-half slab
            const uint32_t k0b = ks * 32;      // 16 halves = 32 B
            uint32_t a[2][4], bb[4][4];
            #pragma unroll
            for (int f = 0; f < 2; f++)
                ldsm4(a[f], As + a_base0 + f * (16 * 128) +
                             ((a_kb + k0b) ^ a_swz0));
            #pragma unroll
            for (int p = 0; p < 4; p++)
                ldsm4(bb[p], Bs + b_base0 + p * (16 * 128) +
                             ((b_kb + k0b) ^ b_swz0));
            #pragma unroll
            for (int f = 0; f < 2; f++)
                #pragma unroll
                for (int p = 0; p < 4; p++) {
                    mma_f16(acc[f][2 * p],     a[f], bb[p][0], bb[p][1]);
                    mma_f16(acc[f][2 * p + 1], a[f], bb[p][2], bb[p][3]);
                }
        }
        __syncthreads();

        if (k + 2 < NSLAB) {
            #pragma unroll
            for (int i = 0; i < 4; i++) {
                cp16(A0 + s * A_STAGE + (adst ^ (i * 16)),
                     xsrc + (k + 2) * BKH + i * 8);
                cp16(B0 + s * B_STAGE + (adst ^ (i * 16)),
                     wsrc + (k + 2) * BKH + i * 8);
            }
        }
        CP_COMMIT();
    }

    // fused scatter epilogue
    const int g  = lid >> 2;
    const int nc = 2 * (lid & 3);
    const int nbase = n0 + wn * 64;
    #pragma unroll
    for (int f = 0; f < 2; f++) {
        #pragma unroll
        for (int h = 0; h < 2; h++) {
            const int m = m0 + wm * 32 + f * 16 + h * 8 + g;
            const int b = m / VV;
            const int t = g_vis[m];
            const float* ve   = view_embed + (t >= T1 ? DEC : 0) + nbase;
            const float* bi   = bias + nbase;
            const float* prow = pos_embed + (size_t)t * DEC + nbase;
            float* orow = out + ((size_t)b * T2 + t) * DEC + nbase;
            #pragma unroll
            for (int nf = 0; nf < 8; nf++) {
                const int n = nf * 8 + nc;
                float2 biv = *(const float2*)(bi + n);
                float2 pov = *(const float2*)(prow + n);
                float2 vev = *(const float2*)(ve + n);
                float2 r;
                r.x = acc[f][nf][2 * h + 0] + biv.x + pov.x + vev.x;
                r.y = acc[f][nf][2 * h + 1] + biv.y + pov.y + vev.y;
                *(float2*)(orow + n) = r;
            }
        }
    }
}

// ---------------------------------------------------------------------------
extern "C" void kernel_launch(void* const* d_in, const int* in_sizes, int n_in,
                              void* d_out, int out_size) {
    const float* x          = (const float*)d_in[0];
    const void*  masked_ids = d_in[1];
    const float* W          = (const float*)d_in[2];
    const float* bias       = (const float*)d_in[3];
    const float* mask_token = (const float*)d_in[4];
    const float* pos_embed  = (const float*)d_in[5];
    const float* view_embed = (const float*)d_in[6];
    float* out = (float*)d_out;

    static int inited = 0;
    static cudaStream_t s1;
    static cudaEvent_t evFork, evJoin;
    if (!inited) {
        cudaStreamCreateWithFlags(&s1, cudaStreamNonBlocking);
        cudaEventCreateWithFlags(&evFork, cudaEventDisableTiming);
        cudaEventCreateWithFlags(&evJoin, cudaEventDisableTiming);
        cudaFuncSetAttribute(gemm_tc_kernel,
                             cudaFuncAttributeMaxDynamicSharedMemorySize,
                             SMEM_DYN);
        inited = 1;
    }

    // stream 0: map + conversions
    prep_kernel<<<PREPB, 512>>>(x, masked_ids, W);

    // fork: fill runs on s1 concurrently with the gemm on stream 0
    cudaEventRecord(evFork, 0);
    cudaStreamWaitEvent(s1, evFork, 0);
    fill_kernel<<<FILLB, 512, 0, s1>>>(masked_ids, mask_token, pos_embed,
                                       view_embed, (float4*)out);

    // stream 0: gemm (writes visible rows; disjoint from fill's masked rows)
    dim3 grid(DEC / BN, (BATCH * VV) / BM);  // (4, 98)
    gemm_tc_kernel<<<grid, 256, SMEM_DYN>>>(bias, pos_embed, view_embed, out);

    // join
    cudaEventRecord(evJoin, s1);
    cudaStreamWaitEvent(0, evJoin, 0);
}